// round 1
// baseline (speedup 1.0000x reference)
#include <cuda_runtime.h>
#include <math.h>

// Problem constants
#define HH 1536
#define WW 1536
#define GXN (WW / 4)            // 384 float4 groups per row
#define NPIX (HH * WW)          // per-channel pixels
#define NP (10 * HH * WW)       // phi elements
#define NTHREADS 256
#define NGROUPS (HH * GXN)      // 589824 thread-work items
#define NBLOCKS (NGROUPS / NTHREADS) // 2304

// Global scratch for channel sums (allocation-free rule: __device__ global)
__device__ double g_sums[10];

// ---------------- float4 helpers ----------------
__device__ __forceinline__ float4 mk4(float a, float b, float c, float d) {
    return make_float4(a, b, c, d);
}
__device__ __forceinline__ float4 operator+(const float4& a, const float4& b) {
    return mk4(a.x + b.x, a.y + b.y, a.z + b.z, a.w + b.w);
}
__device__ __forceinline__ float4 operator-(const float4& a, const float4& b) {
    return mk4(a.x - b.x, a.y - b.y, a.z - b.z, a.w - b.w);
}
__device__ __forceinline__ float4 operator*(float s, const float4& a) {
    return mk4(s * a.x, s * a.y, s * a.z, s * a.w);
}
__device__ __forceinline__ float4& operator+=(float4& a, const float4& b) {
    a.x += b.x; a.y += b.y; a.z += b.z; a.w += b.w; return a;
}
// x-shift permutes: value at x-1 / x+1 / x-2 / x+2 for the 4-lane group
__device__ __forceinline__ float4 shl1(const float4& L, const float4& C) {
    return mk4(L.w, C.x, C.y, C.z);
}
__device__ __forceinline__ float4 shr1(const float4& C, const float4& R) {
    return mk4(C.y, C.z, C.w, R.x);
}
__device__ __forceinline__ float4 shl2(const float4& L, const float4& C) {
    return mk4(L.z, L.w, C.x, C.y);
}
__device__ __forceinline__ float4 shr2(const float4& C, const float4& R) {
    return mk4(C.z, C.w, R.x, R.y);
}
__device__ __forceinline__ float4 clamp4(const float4& a, float lo, float hi) {
    return mk4(fminf(fmaxf(a.x, lo), hi), fminf(fmaxf(a.y, lo), hi),
               fminf(fmaxf(a.z, lo), hi), fminf(fmaxf(a.w, lo), hi));
}
__device__ __forceinline__ float4 fabs4(const float4& a) {
    return mk4(fabsf(a.x), fabsf(a.y), fabsf(a.z), fabsf(a.w));
}

// Per-channel reaction term (c is compile-time constant after unroll)
__device__ __forceinline__ float react(int c, float p, float lap, float bil,
                                        float g, float a0) {
    float p2 = p * p;
    float p3 = p2 * p;
    switch (c) {
        case 0: return -g * lap - a0 * p3 + 0.12f * bil;
        case 1: return -g * lap + 0.15f * sinf(p) + 0.08f * p3;
        case 2: return -g * lap + 0.2f * p * (1.0f - p2);
        case 3: return -g * lap - 0.03f * p3 * p2 + 0.08f * bil;
        case 4: return -g * lap + 0.12f * p * logf(fabsf(p) + 1e-6f) + 0.02f * bil;
        case 5: return -g * lap + 0.08f * p3 - 0.02f * p3 * p2;
        case 6: return -g * lap + 0.06f * p2 * p2 - 0.04f * p;
        case 7: return -g * lap + 0.08f * sinhf(fminf(fmaxf(p, -2.0f), 2.0f));
        case 8: return -g * lap + 0.05f * p2 - 0.08f * p;
        case 9: return -g * lap + 0.02f * p3 * p3 - 0.04f * p3 + 0.01f * bil;
    }
    return 0.0f;
}

__global__ void zero_sums_kernel() {
    if (threadIdx.x < 10) g_sums[threadIdx.x] = 0.0;
}

__global__ void __launch_bounds__(NTHREADS, 2)
step_kernel(const float* __restrict__ phi,
            const float* __restrict__ sens,
            const float* __restrict__ gam,
            const float* __restrict__ alp,
            const float* __restrict__ mixw,
            float* __restrict__ out) {
    __shared__ float sw[100];
    __shared__ float sg[10];
    __shared__ float sred[NTHREADS / 32][10];

    const int tid = threadIdx.x;
    if (tid < 100) sw[tid] = mixw[tid];
    if (tid < 10) sg[tid] = gam[tid];
    const float a0 = alp[0];
    __syncthreads();

    const int g = blockIdx.x * NTHREADS + tid;
    const int y = g / GXN;
    const int gx = g - y * GXN;

    // Periodic wrap indices
    const int ym1 = y ? y - 1 : HH - 1;
    const int yp1 = (y == HH - 1) ? 0 : y + 1;
    const int ym2 = (y >= 2) ? y - 2 : y + HH - 2;
    const int yp2 = (y < HH - 2) ? y + 2 : y + 2 - HH;
    const int gxm1 = gx ? gx - 1 : GXN - 1;
    const int gxp1 = (gx == GXN - 1) ? 0 : gx + 1;

    const float4* __restrict__ P = reinterpret_cast<const float4*>(phi);
    float4* __restrict__ O = reinterpret_cast<float4*>(out);

    // Load all channel centers (kept in registers for coupling/means)
    float4 cen[10];
#pragma unroll
    for (int c = 0; c < 10; c++) {
        cen[c] = P[(c * HH + y) * GXN + gx];
    }

    const float4 fm = 0.2f * (cen[0] + cen[1] + cen[2] + cen[3] + cen[4]);
    const float4 sm = 0.2f * (cen[5] + cen[6] + cen[7] + cen[8] + cen[9]);
    const float4 sd = reinterpret_cast<const float4*>(sens)[y * GXN + gx];
    const float4 asd = fabs4(sd);

    float chsum[10];

#pragma unroll
    for (int c = 0; c < 10; c++) {
        const int pb = c * HH;
        const float4 C = cen[c];
        const float4 uC = P[(pb + ym1) * GXN + gx];
        const float4 dC = P[(pb + yp1) * GXN + gx];
        const float4 L = P[(pb + y) * GXN + gxm1];
        const float4 R = P[(pb + y) * GXN + gxp1];
        const float4 sl = shl1(L, C);
        const float4 sr = shr1(C, R);
        const float4 s4 = uC + dC + sl + sr;
        const float4 lap = s4 - 4.0f * C;

        float4 bil = mk4(0.f, 0.f, 0.f, 0.f);
        const bool needB = (c == 0 || c == 3 || c == 4 || c == 9);
        if (needB) {
            const float4 uL = P[(pb + ym1) * GXN + gxm1];
            const float4 uR = P[(pb + ym1) * GXN + gxp1];
            const float4 dL = P[(pb + yp1) * GXN + gxm1];
            const float4 dR = P[(pb + yp1) * GXN + gxp1];
            const float4 uu = P[(pb + ym2) * GXN + gx];
            const float4 dd = P[(pb + yp2) * GXN + gx];
            const float4 diag = shl1(uL, uC) + shr1(uC, uR) + shl1(dL, dC) + shr1(dC, dR);
            const float4 ring2 = uu + dd + shl2(L, C) + shr2(C, R);
            bil = 20.0f * C - 8.0f * s4 + 2.0f * diag + ring2;
        }

        const float gc = sg[c];
        float4 dv;
        dv.x = react(c, C.x, lap.x, bil.x, gc, a0);
        dv.y = react(c, C.y, lap.y, bil.y, gc, a0);
        dv.z = react(c, C.z, lap.z, bil.z, gc, a0);
        dv.w = react(c, C.w, lap.w, bil.w, gc, a0);

        // Channel coupling: mix_w[c,:] . cen[:]
        float4 coup = mk4(0.f, 0.f, 0.f, 0.f);
#pragma unroll
        for (int k = 0; k < 10; k++) {
            const float w = sw[c * 10 + k];
            coup += w * cen[k];
        }

        float dtc;
        if (c < 5) {
            dv += 0.06f * coup;   // EPS_FAST
            dv += 0.02f * sm;     // S2F * slow_mean
            dtc = 0.02f;          // DT * FAST_DT
        } else {
            dv += 0.02f * coup;   // EPS_SLOW
            dv += 0.04f * fm;     // F2S * fast_mean
            dtc = 0.004f;         // DT * SLOW_DT
        }
        if (c == 0) dv += 0.2f * sd;
        if (c == 4) dv += 0.08f * asd;
        if (c == 9) dv += 0.05f * sd;

        const float4 r = clamp4(C + dtc * dv, -4.0f, 4.0f);
        O[(pb + y) * GXN + gx] = r;
        chsum[c] = r.x + r.y + r.z + r.w;
    }

    // Block reduction of channel sums
    const int lane = tid & 31;
    const int wrp = tid >> 5;
#pragma unroll
    for (int c = 0; c < 10; c++) {
        float v = chsum[c];
#pragma unroll
        for (int off = 16; off; off >>= 1)
            v += __shfl_down_sync(0xffffffffu, v, off);
        if (lane == 0) sred[wrp][c] = v;
    }
    __syncthreads();
    if (tid < 10) {
        float s = 0.0f;
#pragma unroll
        for (int w2 = 0; w2 < NTHREADS / 32; w2++) s += sred[w2][tid];
        atomicAdd(&g_sums[tid], (double)s);
    }
}

__global__ void finalize_kernel(float* __restrict__ out) {
    const int t = threadIdx.x;
    if (t < 10) {
        const float m = (float)(g_sums[t] / (double)NPIX);
        out[NP + 2 + t] = m;          // field_means[t]
        if (t == 0) out[NP] = m;      // phi1_mean
        if (t == 4) out[NP + 1] = m;  // phi5_mean
    }
}

extern "C" void kernel_launch(void* const* d_in, const int* in_sizes, int n_in,
                              void* d_out, int out_size) {
    const float* phi  = (const float*)d_in[0];
    const float* sens = (const float*)d_in[1];
    const float* gam  = (const float*)d_in[2];
    const float* alp  = (const float*)d_in[3];
    const float* mixw = (const float*)d_in[4];
    float* out = (float*)d_out;

    zero_sums_kernel<<<1, 32>>>();
    step_kernel<<<NBLOCKS, NTHREADS>>>(phi, sens, gam, alp, mixw, out);
    finalize_kernel<<<1, 32>>>(out);
}